// round 10
// baseline (speedup 1.0000x reference)
#include <cuda_runtime.h>
#include <cuda_bf16.h>
#include <math.h>

#define N_NODES 50000
#define N_EDGES 800000
#define DIM 64

// ---- static scratch ----
__device__ __align__(16) float g_p[N_NODES * DIM];   // h @ w_flat^T
__device__ __align__(16) float g_A[N_NODES * 8];     // per-node unnormalized accumulator
__device__ __align__(8)  float2 g_sd[N_NODES];       // (s, d) per node
__device__ float g_denom[N_NODES];

// ============================================================================
// k_node: 64-node tile -> p[n,:], (s,d)[n]; zero denom/A.
// 128 threads, 4x8 register microtile; 32KB smem -> 7 blocks/SM, grid 782.
// ============================================================================
__global__ void __launch_bounds__(128, 7) k_node(
    const float* __restrict__ h, const float* __restrict__ w,
    const float* __restrict__ attn) {
    __shared__ float sHt[DIM * 64];   // sHt[i*64 + r] = h[n0+r][i]
    __shared__ float sWt[DIM * 64];   // sWt[i*64 + o] = w[o*64 + i]

    int tid = threadIdx.x;
    int n0 = blockIdx.x * 64;
    int nrem = N_NODES - n0;          // last block: 16

    int row  = tid & 63;              // matrix row this thread transposes
    int half = tid >> 6;              // which 32-column chunk (0/1)

    // --- W fill: thread (row,half) loads 8 float4 of w[row], stores transposed.
    {
        const float4* wrow = reinterpret_cast<const float4*>(w + row * DIM) + half * 8;
#pragma unroll
        for (int c4 = 0; c4 < 8; c4++) {
            float4 v = __ldg(wrow + c4);
            int c = half * 32 + c4 * 4;
            sWt[(c + 0) * 64 + row] = v.x;
            sWt[(c + 1) * 64 + row] = v.y;
            sWt[(c + 2) * 64 + row] = v.z;
            sWt[(c + 3) * 64 + row] = v.w;
        }
    }
    // --- H fill ---
    {
        bool valid = (row < nrem);
        const float4* hrow = reinterpret_cast<const float4*>(
            h + (size_t)(n0 + (valid ? row : 0)) * DIM) + half * 8;
        float4 z = make_float4(0.f, 0.f, 0.f, 0.f);
#pragma unroll
        for (int c4 = 0; c4 < 8; c4++) {
            float4 v = valid ? __ldg(hrow + c4) : z;
            int c = half * 32 + c4 * 4;
            sHt[(c + 0) * 64 + row] = v.x;
            sHt[(c + 1) * 64 + row] = v.y;
            sHt[(c + 2) * 64 + row] = v.z;
            sHt[(c + 3) * 64 + row] = v.w;
        }
    }
    __syncthreads();

    // --- 4x8 microtile: nodes 4*nq.., outputs 8*oq.. ---
    int nq = tid >> 3;        // 0..15
    int oq = tid & 7;         // 0..7
    float acc[4][8];
#pragma unroll
    for (int a = 0; a < 4; a++)
#pragma unroll
        for (int b = 0; b < 8; b++) acc[a][b] = 0.0f;

#pragma unroll 4
    for (int i = 0; i < DIM; i++) {
        float4 hn = *reinterpret_cast<const float4*>(&sHt[i * 64 + 4 * nq]);
        const float4* wp = reinterpret_cast<const float4*>(&sWt[i * 64 + 8 * oq]);
        float4 w0 = wp[0], w1 = wp[1];
        float hv[4] = {hn.x, hn.y, hn.z, hn.w};
        float wv[8] = {w0.x, w0.y, w0.z, w0.w, w1.x, w1.y, w1.z, w1.w};
#pragma unroll
        for (int a = 0; a < 4; a++)
#pragma unroll
            for (int b = 0; b < 8; b++) acc[a][b] = fmaf(hv[a], wv[b], acc[a][b]);
    }
#pragma unroll
    for (int a = 0; a < 4; a++) {
        int rl = 4 * nq + a;
        if (rl < nrem) {
            float* dst = &g_p[(size_t)(n0 + rl) * DIM + 8 * oq];
            *reinterpret_cast<float4*>(dst) =
                make_float4(acc[a][0], acc[a][1], acc[a][2], acc[a][3]);
            *reinterpret_cast<float4*>(dst + 4) =
                make_float4(acc[a][4], acc[a][5], acc[a][6], acc[a][7]);
        }
    }

    // --- per-node attention scalars + zero init ---
    if (tid < 64 && tid < nrem) {
        float s = 0.f, d = 0.f;
#pragma unroll 8
        for (int i = 0; i < DIM; i++) {
            float hv = sHt[i * 64 + tid];
            s = fmaf(hv, __ldg(attn + i), s);
            d = fmaf(hv, __ldg(attn + 64 + i), d);
        }
        int n = n0 + tid;
        g_sd[n] = make_float2(s, d);
        g_denom[n] = 0.0f;
    }
    if (tid * 4 < nrem * 8) {
        *reinterpret_cast<float4*>(&g_A[n0 * 8 + tid * 4]) =
            make_float4(0.f, 0.f, 0.f, 0.f);
    }
}

// ============================================================================
// Fused edge pass: denom[dn] += ex ; A[dn] += ex * p[sn, 8r..8r+7].
// ============================================================================
__global__ void k_edge(const int* __restrict__ src, const int* __restrict__ dst,
                       const int* __restrict__ we) {
    int e = blockIdx.x * blockDim.x + threadIdx.x;
    if (e >= N_EDGES) return;
    int sn = src[e], dn = dst[e], r = we[e];
    float x = __ldg(&g_sd[sn].x) + __ldg(&g_sd[dn].y);
    float v = (x > 0.0f) ? x : 0.01f * x;
    float ex = __expf(v);
    const float4* pr = reinterpret_cast<const float4*>(g_p + sn * DIM + r * 8);
    float4 p0 = __ldg(pr), p1 = __ldg(pr + 1);
    atomicAdd(&g_denom[dn], ex);
    float4* arow = reinterpret_cast<float4*>(g_A + dn * 8);
    atomicAdd(&arow[0], make_float4(ex * p0.x, ex * p0.y, ex * p0.z, ex * p0.w));
    atomicAdd(&arow[1], make_float4(ex * p1.x, ex * p1.y, ex * p1.z, ex * p1.w));
}

// ============================================================================
// Expand: out[n, o] = w_comp[o & 7] * A[n, o >> 3] / max(denom[n], 1e-38).
// ============================================================================
#define HALF_F4 (N_NODES * 8)
__global__ void k_expand(const float* __restrict__ w_comp, float* __restrict__ out) {
    int t = blockIdx.x * blockDim.x + threadIdx.x;
    if (t >= HALF_F4) return;
    float4 wc0 = __ldg(reinterpret_cast<const float4*>(w_comp));
    float4 wc1 = __ldg(reinterpret_cast<const float4*>(w_comp) + 1);
#pragma unroll
    for (int half = 0; half < 2; half++) {
        int t4 = t + half * HALF_F4;
        int n = t4 >> 4;
        int k = t4 & 15;
        float inv = __fdividef(1.0f, fmaxf(g_denom[n], 1e-38f));
        float a = g_A[n * 8 + (k >> 1)] * inv;
        float4 wc = (k & 1) ? wc1 : wc0;
        reinterpret_cast<float4*>(out)[t4] =
            make_float4(a * wc.x, a * wc.y, a * wc.z, a * wc.w);
    }
}

extern "C" void kernel_launch(void* const* d_in, const int* in_sizes, int n_in,
                              void* d_out, int out_size) {
    const float* h      = (const float*)d_in[0];
    const int*   src    = (const int*)d_in[1];
    const int*   dst    = (const int*)d_in[2];
    const int*   we     = (const int*)d_in[3];
    const float* w      = (const float*)d_in[4];
    const float* w_comp = (const float*)d_in[5];
    const float* attn   = (const float*)d_in[6];
    float* out = (float*)d_out;
    (void)in_sizes; (void)n_in; (void)out_size;

    k_node<<<(N_NODES + 63) / 64, 128>>>(h, w, attn);
    k_edge<<<(N_EDGES + 255) / 256, 256>>>(src, dst, we);
    k_expand<<<(HALF_F4 + 255) / 256, 256>>>(w_comp, out);
}

// round 11
// speedup vs baseline: 1.0254x; 1.0254x over previous
#include <cuda_runtime.h>
#include <cuda_bf16.h>
#include <math.h>

#define N_NODES 50000
#define N_EDGES 800000
#define DIM 64

// ---- static scratch ----
__device__ __align__(16) float g_p[N_NODES * DIM];   // h @ w_flat^T
__device__ __align__(16) float g_A[N_NODES * 8];     // per-node unnormalized accumulator
__device__ float g_s[N_NODES];
__device__ float g_d[N_NODES];
__device__ float g_denom[N_NODES];

// ============================================================================
// k_node: 128-node x 64-out tile, 256 threads, 4x8 register microtile.
// 48KB smem, <=64 regs -> 4 blocks/SM = 32 warps/SM (50% occ) for latency hiding.
// All smem fills/reads conflict-free (lane == row on STS; warp-deduped LDS.128).
// ============================================================================
__global__ void __launch_bounds__(256, 4) k_node(
    const float* __restrict__ h, const float* __restrict__ w,
    const float* __restrict__ attn) {
    __shared__ float sHt[DIM * 128];  // sHt[i*128 + r] = h[n0+r][i]   (32KB)
    __shared__ float sWt[DIM * 64];   // sWt[i*64 + o]  = w[o*64 + i]  (16KB)

    int tid = threadIdx.x;
    int n0 = blockIdx.x * 128;
    int nrem = N_NODES - n0;          // last block: 80

    // --- W fill: 256 threads; thread = (row 0..63, quarter 0..3), 4 float4 each ---
    {
        int row = tid & 63;
        int q   = tid >> 6;           // 0..3
        const float4* wrow = reinterpret_cast<const float4*>(w + row * DIM) + q * 4;
#pragma unroll
        for (int k = 0; k < 4; k++) {
            float4 v = __ldg(wrow + k);
            int c = (q * 4 + k) * 4;
            sWt[(c + 0) * 64 + row] = v.x;
            sWt[(c + 1) * 64 + row] = v.y;
            sWt[(c + 2) * 64 + row] = v.z;
            sWt[(c + 3) * 64 + row] = v.w;
        }
    }
    // --- H fill: thread = (row 0..127, half 0..1), 8 float4 each ---
    {
        int r    = tid & 127;
        int half = tid >> 7;          // 0..1
        bool valid = (r < nrem);
        const float4* hrow = reinterpret_cast<const float4*>(
            h + (size_t)(n0 + (valid ? r : 0)) * DIM) + half * 8;
        float4 z = make_float4(0.f, 0.f, 0.f, 0.f);
#pragma unroll
        for (int k = 0; k < 8; k++) {
            float4 v = valid ? __ldg(hrow + k) : z;
            int c = (half * 8 + k) * 4;
            sHt[(c + 0) * 128 + r] = v.x;
            sHt[(c + 1) * 128 + r] = v.y;
            sHt[(c + 2) * 128 + r] = v.z;
            sHt[(c + 3) * 128 + r] = v.w;
        }
    }
    __syncthreads();

    // --- 4x8 microtile: nodes 4*nq (nq 0..31), outputs 8*oq (oq 0..7) ---
    int nq = tid >> 3;
    int oq = tid & 7;
    float acc[4][8];
#pragma unroll
    for (int a = 0; a < 4; a++)
#pragma unroll
        for (int b = 0; b < 8; b++) acc[a][b] = 0.0f;

#pragma unroll 4
    for (int i = 0; i < DIM; i++) {
        float4 hn = *reinterpret_cast<const float4*>(&sHt[i * 128 + 4 * nq]);
        const float4* wp = reinterpret_cast<const float4*>(&sWt[i * 64 + 8 * oq]);
        float4 w0 = wp[0], w1 = wp[1];
        float hv[4] = {hn.x, hn.y, hn.z, hn.w};
        float wv[8] = {w0.x, w0.y, w0.z, w0.w, w1.x, w1.y, w1.z, w1.w};
#pragma unroll
        for (int a = 0; a < 4; a++)
#pragma unroll
            for (int b = 0; b < 8; b++) acc[a][b] = fmaf(hv[a], wv[b], acc[a][b]);
    }
#pragma unroll
    for (int a = 0; a < 4; a++) {
        int rl = 4 * nq + a;
        if (rl < nrem) {
            float* dst = &g_p[(size_t)(n0 + rl) * DIM + 8 * oq];
            *reinterpret_cast<float4*>(dst) =
                make_float4(acc[a][0], acc[a][1], acc[a][2], acc[a][3]);
            *reinterpret_cast<float4*>(dst + 4) =
                make_float4(acc[a][4], acc[a][5], acc[a][6], acc[a][7]);
        }
    }

    // --- per-node attention scalars + zero init (threads 0..127 = one node each) ---
    if (tid < 128 && tid < nrem) {
        float s = 0.f, d = 0.f;
#pragma unroll 8
        for (int i = 0; i < DIM; i++) {
            float hv = sHt[i * 128 + tid];
            s = fmaf(hv, __ldg(attn + i), s);
            d = fmaf(hv, __ldg(attn + 64 + i), d);
        }
        int n = n0 + tid;
        g_s[n] = s;
        g_d[n] = d;
        g_denom[n] = 0.0f;
    }
    if (tid * 4 < nrem * 8) {
        *reinterpret_cast<float4*>(&g_A[n0 * 8 + tid * 4]) =
            make_float4(0.f, 0.f, 0.f, 0.f);
    }
}

// ============================================================================
// Fused edge pass (R9-proven): denom[dn] += ex ; A[dn] += ex * p[sn, 8r..8r+7].
// ============================================================================
__global__ void k_edge(const int* __restrict__ src, const int* __restrict__ dst,
                       const int* __restrict__ we) {
    int e = blockIdx.x * blockDim.x + threadIdx.x;
    if (e >= N_EDGES) return;
    int sn = src[e], dn = dst[e], r = we[e];
    float x = __ldg(&g_s[sn]) + __ldg(&g_d[dn]);
    float v = (x > 0.0f) ? x : 0.01f * x;
    float ex = __expf(v);
    const float4* pr = reinterpret_cast<const float4*>(g_p + sn * DIM + r * 8);
    float4 p0 = __ldg(pr), p1 = __ldg(pr + 1);
    atomicAdd(&g_denom[dn], ex);
    float4* arow = reinterpret_cast<float4*>(g_A + dn * 8);
    atomicAdd(&arow[0], make_float4(ex * p0.x, ex * p0.y, ex * p0.z, ex * p0.w));
    atomicAdd(&arow[1], make_float4(ex * p1.x, ex * p1.y, ex * p1.z, ex * p1.w));
}

// ============================================================================
// Expand (R9-proven): out[n, o] = w_comp[o & 7] * A[n, o >> 3] / max(denom, 1e-38).
// ============================================================================
#define HALF_F4 (N_NODES * 8)
__global__ void k_expand(const float* __restrict__ w_comp, float* __restrict__ out) {
    int t = blockIdx.x * blockDim.x + threadIdx.x;
    if (t >= HALF_F4) return;
    float4 wc0 = __ldg(reinterpret_cast<const float4*>(w_comp));
    float4 wc1 = __ldg(reinterpret_cast<const float4*>(w_comp) + 1);
#pragma unroll
    for (int half = 0; half < 2; half++) {
        int t4 = t + half * HALF_F4;
        int n = t4 >> 4;
        int k = t4 & 15;
        float inv = __fdividef(1.0f, fmaxf(g_denom[n], 1e-38f));
        float a = g_A[n * 8 + (k >> 1)] * inv;
        float4 wc = (k & 1) ? wc1 : wc0;
        reinterpret_cast<float4*>(out)[t4] =
            make_float4(a * wc.x, a * wc.y, a * wc.z, a * wc.w);
    }
}

extern "C" void kernel_launch(void* const* d_in, const int* in_sizes, int n_in,
                              void* d_out, int out_size) {
    const float* h      = (const float*)d_in[0];
    const int*   src    = (const int*)d_in[1];
    const int*   dst    = (const int*)d_in[2];
    const int*   we     = (const int*)d_in[3];
    const float* w      = (const float*)d_in[4];
    const float* w_comp = (const float*)d_in[5];
    const float* attn   = (const float*)d_in[6];
    float* out = (float*)d_out;
    (void)in_sizes; (void)n_in; (void)out_size;

    k_node<<<(N_NODES + 127) / 128, 256>>>(h, w, attn);
    k_edge<<<(N_EDGES + 255) / 256, 256>>>(src, dst, we);
    k_expand<<<(HALF_F4 + 255) / 256, 256>>>(w_comp, out);
}

// round 12
// speedup vs baseline: 1.7536x; 1.7101x over previous
#include <cuda_runtime.h>
#include <cuda_bf16.h>
#include <math.h>

#define N_NODES 50000
#define N_EDGES 800000
#define DIM 64

// ---- static scratch ----
__device__ __align__(16) float g_p[N_NODES * DIM];   // h @ w_flat^T
__device__ __align__(16) float g_A[N_NODES * 8];     // per-node unnormalized accumulator
__device__ float g_s[N_NODES];
__device__ float g_d[N_NODES];
__device__ float g_denom[N_NODES];

union F4U { float4 f; unsigned long long u[2]; };

__device__ __forceinline__ unsigned long long f32x2_dup(float x) {
    unsigned long long r;
    unsigned int xi = __float_as_uint(x);
    asm("mov.b64 %0, {%1, %1};" : "=l"(r) : "r"(xi));
    return r;
}
__device__ __forceinline__ unsigned long long fma_f32x2(
    unsigned long long a, unsigned long long b, unsigned long long c) {
    unsigned long long d;
    asm("fma.rn.f32x2 %0, %1, %2, %3;" : "=l"(d) : "l"(a), "l"(b), "l"(c));
    return d;
}

// ============================================================================
// k_node: 128-node x 64-out tile, 128 threads, 8x8 microtile via fma.rn.f32x2
// (FFMA2: 2 FMA/instr, halves the fp32 issue floor). W tile in a slab layout
// (stride 516 floats) making the 8-lane 16B reads conflict-free by construction.
// ============================================================================
__global__ void __launch_bounds__(128) k_node(
    const float* __restrict__ h, const float* __restrict__ w,
    const float* __restrict__ attn) {
    __shared__ float sHt[DIM * 128];   // sHt[i*128 + r] = h[n0+r][i]       (32KB)
    __shared__ float sWtS[8 * 516];    // sWtS[oq*516 + i*8 + k] = w[(8oq+k)*64 + i]

    int tid = threadIdx.x;
    int n0 = blockIdx.x * 128;
    int nrem = N_NODES - n0;           // last block: 80

    // --- W fill: thread = (row o = tid&63, half = tid>>6); slab-transposed STS ---
    {
        int o = tid & 63;
        int half = tid >> 6;           // i-range half*32 .. +32
        int oq = o >> 3, k = o & 7;
        const float4* wrow = reinterpret_cast<const float4*>(w + o * DIM) + half * 8;
        float* slab = &sWtS[oq * 516 + k];
#pragma unroll
        for (int j = 0; j < 8; j++) {
            float4 v = __ldg(wrow + j);
            int i0 = half * 32 + j * 4;
            slab[(i0 + 0) * 8] = v.x;
            slab[(i0 + 1) * 8] = v.y;
            slab[(i0 + 2) * 8] = v.z;
            slab[(i0 + 3) * 8] = v.w;
        }
    }
    // --- H fill: thread r transposes row n0+r (16 float4) ---
    {
        int r = tid;
        bool valid = (r < nrem);
        const float4* hrow = reinterpret_cast<const float4*>(
            h + (size_t)(n0 + (valid ? r : 0)) * DIM);
        float4 z = make_float4(0.f, 0.f, 0.f, 0.f);
#pragma unroll
        for (int c4 = 0; c4 < 16; c4++) {
            float4 v = valid ? __ldg(hrow + c4) : z;
            int c = c4 * 4;
            sHt[(c + 0) * 128 + r] = v.x;
            sHt[(c + 1) * 128 + r] = v.y;
            sHt[(c + 2) * 128 + r] = v.z;
            sHt[(c + 3) * 128 + r] = v.w;
        }
    }
    __syncthreads();

    // --- 8x8 microtile: nodes 8*nq (nq 0..15), outputs 8*oq (oq 0..7) ---
    int nq = tid >> 3;
    int oq = tid & 7;
    unsigned long long acc[8][4];      // acc[a][bp] = (out 2bp, out 2bp+1) for node a
#pragma unroll
    for (int a = 0; a < 8; a++)
#pragma unroll
        for (int bp = 0; bp < 4; bp++) acc[a][bp] = 0ull;

    const float* wslab = &sWtS[oq * 516];

#pragma unroll 4
    for (int i = 0; i < DIM; i++) {
        const float4* hp = reinterpret_cast<const float4*>(&sHt[i * 128 + 8 * nq]);
        float4 h0 = hp[0], h1 = hp[1];
        F4U w0, w1;
        w0.f = *reinterpret_cast<const float4*>(wslab + i * 8);
        w1.f = *reinterpret_cast<const float4*>(wslab + i * 8 + 4);
        unsigned long long wp[4] = {w0.u[0], w0.u[1], w1.u[0], w1.u[1]};
        float hv[8] = {h0.x, h0.y, h0.z, h0.w, h1.x, h1.y, h1.z, h1.w};
#pragma unroll
        for (int a = 0; a < 8; a++) {
            unsigned long long ha = f32x2_dup(hv[a]);
#pragma unroll
            for (int bp = 0; bp < 4; bp++)
                acc[a][bp] = fma_f32x2(ha, wp[bp], acc[a][bp]);
        }
    }
#pragma unroll
    for (int a = 0; a < 8; a++) {
        int rl = 8 * nq + a;
        if (rl < nrem) {
            F4U o0, o1;
            o0.u[0] = acc[a][0]; o0.u[1] = acc[a][1];
            o1.u[0] = acc[a][2]; o1.u[1] = acc[a][3];
            float* dst = &g_p[(size_t)(n0 + rl) * DIM + 8 * oq];
            *reinterpret_cast<float4*>(dst) = o0.f;
            *reinterpret_cast<float4*>(dst + 4) = o1.f;
        }
    }

    // --- per-node attention scalars + zero init (one node per thread) ---
    if (tid < nrem) {
        float s = 0.f, d = 0.f;
#pragma unroll 8
        for (int i = 0; i < DIM; i++) {
            float hv = sHt[i * 128 + tid];
            s = fmaf(hv, __ldg(attn + i), s);
            d = fmaf(hv, __ldg(attn + 64 + i), d);
        }
        int n = n0 + tid;
        g_s[n] = s;
        g_d[n] = d;
        g_denom[n] = 0.0f;
        float4 z = make_float4(0.f, 0.f, 0.f, 0.f);
        *reinterpret_cast<float4*>(&g_A[n * 8]) = z;
        *reinterpret_cast<float4*>(&g_A[n * 8 + 4]) = z;
    }
}

// ============================================================================
// Fused edge pass (R9-proven): denom[dn] += ex ; A[dn] += ex * p[sn, 8r..8r+7].
// ============================================================================
__global__ void k_edge(const int* __restrict__ src, const int* __restrict__ dst,
                       const int* __restrict__ we) {
    int e = blockIdx.x * blockDim.x + threadIdx.x;
    if (e >= N_EDGES) return;
    int sn = src[e], dn = dst[e], r = we[e];
    float x = __ldg(&g_s[sn]) + __ldg(&g_d[dn]);
    float v = (x > 0.0f) ? x : 0.01f * x;
    float ex = __expf(v);
    const float4* pr = reinterpret_cast<const float4*>(g_p + sn * DIM + r * 8);
    float4 p0 = __ldg(pr), p1 = __ldg(pr + 1);
    atomicAdd(&g_denom[dn], ex);
    float4* arow = reinterpret_cast<float4*>(g_A + dn * 8);
    atomicAdd(&arow[0], make_float4(ex * p0.x, ex * p0.y, ex * p0.z, ex * p0.w));
    atomicAdd(&arow[1], make_float4(ex * p1.x, ex * p1.y, ex * p1.z, ex * p1.w));
}

// ============================================================================
// Expand (R9-proven): out[n, o] = w_comp[o & 7] * A[n, o >> 3] / max(denom, 1e-38).
// ============================================================================
#define HALF_F4 (N_NODES * 8)
__global__ void k_expand(const float* __restrict__ w_comp, float* __restrict__ out) {
    int t = blockIdx.x * blockDim.x + threadIdx.x;
    if (t >= HALF_F4) return;
    float4 wc0 = __ldg(reinterpret_cast<const float4*>(w_comp));
    float4 wc1 = __ldg(reinterpret_cast<const float4*>(w_comp) + 1);
#pragma unroll
    for (int half = 0; half < 2; half++) {
        int t4 = t + half * HALF_F4;
        int n = t4 >> 4;
        int k = t4 & 15;
        float inv = __fdividef(1.0f, fmaxf(g_denom[n], 1e-38f));
        float a = g_A[n * 8 + (k >> 1)] * inv;
        float4 wc = (k & 1) ? wc1 : wc0;
        reinterpret_cast<float4*>(out)[t4] =
            make_float4(a * wc.x, a * wc.y, a * wc.z, a * wc.w);
    }
}

extern "C" void kernel_launch(void* const* d_in, const int* in_sizes, int n_in,
                              void* d_out, int out_size) {
    const float* h      = (const float*)d_in[0];
    const int*   src    = (const int*)d_in[1];
    const int*   dst    = (const int*)d_in[2];
    const int*   we     = (const int*)d_in[3];
    const float* w      = (const float*)d_in[4];
    const float* w_comp = (const float*)d_in[5];
    const float* attn   = (const float*)d_in[6];
    float* out = (float*)d_out;
    (void)in_sizes; (void)n_in; (void)out_size;

    k_node<<<(N_NODES + 127) / 128, 128>>>(h, w, attn);
    k_edge<<<(N_EDGES + 255) / 256, 256>>>(src, dst, we);
    k_expand<<<(HALF_F4 + 255) / 256, 256>>>(w_comp, out);
}